// round 6
// baseline (speedup 1.0000x reference)
#include <cuda_runtime.h>
#include <cstdint>
#include <math_constants.h>

#define N_SPLINES 64
#define C_DIM     64
#define T_DIM     68
#define NJ        67
#define NTH       (2*NJ)      // 134 thresholds per spline
#define NPF       (NTH + 1)   // 135 prefix polynomials (m = 0..134)
#define NB        512         // buckets, width 1/64 over [-4,4)
#define NTHP      140         // padded threshold array: [0]=-INF, [1..134]=th, [135..139]=+INF

// Precomputed per-spline tables
__device__ float   g_th[N_SPLINES][NTHP];
__device__ float4  g_C [N_SPLINES][NPF];     // Taylor coeffs of prefix poly m
__device__ uint8_t g_bt[N_SPLINES][NB];      // bucket -> #{th < edge_b}; bt[0]=0

// ---------------------------------------------------------------------------
// Precompute (fp64): Cox-de Boor -> per-interval cubics -> threshold
// decomposition -> sort -> prefix polys -> Taylor-center -> bucket table.
// ---------------------------------------------------------------------------
__device__ __forceinline__ double sinv(double den) {
    return den == 0.0 ? 0.0 : 1.0 / den;
}

__device__ __forceinline__ void build_p3(const double* st, int i, double p3[4][4]) {
    double p1[3][2][2];
#pragma unroll
    for (int a2 = 0; a2 < 3; ++a2) {
        int a = i + a2;
        double invA = sinv(st[a + 1] - st[a]);
        double invB = sinv(st[a + 2] - st[a + 1]);
        p1[a2][0][0] = -st[a] * invA;
        p1[a2][0][1] = invA;
        p1[a2][1][0] = st[a + 2] * invB;
        p1[a2][1][1] = -invB;
    }
    double p2[2][3][3];
#pragma unroll
    for (int a2 = 0; a2 < 2; ++a2) {
        int a = i + a2;
#pragma unroll
        for (int jj = 0; jj < 3; ++jj)
#pragma unroll
            for (int d = 0; d < 3; ++d) p2[a2][jj][d] = 0.0;
        double invA = sinv(st[a + 2] - st[a]);
        double invB = sinv(st[a + 3] - st[a + 1]);
        double l0 = -st[a] * invA, l1 = invA;
        double r0 = st[a + 3] * invB, r1 = -invB;
#pragma unroll
        for (int jj = 0; jj < 2; ++jj)
#pragma unroll
            for (int d = 0; d < 2; ++d) {
                p2[a2][jj][d]     += l0 * p1[a2][jj][d];
                p2[a2][jj][d + 1] += l1 * p1[a2][jj][d];
            }
#pragma unroll
        for (int jj = 1; jj < 3; ++jj)
#pragma unroll
            for (int d = 0; d < 2; ++d) {
                p2[a2][jj][d]     += r0 * p1[a2 + 1][jj - 1][d];
                p2[a2][jj][d + 1] += r1 * p1[a2 + 1][jj - 1][d];
            }
    }
#pragma unroll
    for (int jj = 0; jj < 4; ++jj)
#pragma unroll
        for (int d = 0; d < 4; ++d) p3[jj][d] = 0.0;
    {
        int a = i;
        double invA = sinv(st[a + 3] - st[a]);
        double invB = sinv(st[a + 4] - st[a + 1]);
        double l0 = -st[a] * invA, l1 = invA;
        double r0 = st[a + 4] * invB, r1 = -invB;
#pragma unroll
        for (int jj = 0; jj < 3; ++jj)
#pragma unroll
            for (int d = 0; d < 3; ++d) {
                p3[jj][d]     += l0 * p2[0][jj][d];
                p3[jj][d + 1] += l1 * p2[0][jj][d];
            }
#pragma unroll
        for (int jj = 1; jj < 4; ++jj)
#pragma unroll
            for (int d = 0; d < 3; ++d) {
                p3[jj][d]     += r0 * p2[1][jj - 1][d];
                p3[jj][d + 1] += r1 * p2[1][jj - 1][d];
            }
    }
}

__global__ void precompute_kernel(const float* __restrict__ t,
                                  const float* __restrict__ c) {
    const int s   = blockIdx.x;
    const int tid = threadIdx.x;

    __shared__ double st[T_DIM];
    __shared__ double sc[C_DIM];
    __shared__ double sP[C_DIM][4][4];
    __shared__ double qm[NJ][4];
    __shared__ float  thr[NTH];
    __shared__ float  sth[NTH];
    __shared__ int    sidx[NTH];
    __shared__ double sv[NTH][4];

    if (tid < T_DIM) st[tid] = (double)t[s * T_DIM + tid];
    if (tid < C_DIM) sc[tid] = (double)c[s * C_DIM + tid];
    __syncthreads();

    // A1: thread i builds p3(i)
    if (tid < C_DIM) {
        double p3[4][4];
        build_p3(st, tid, p3);
#pragma unroll
        for (int jj = 0; jj < 4; ++jj)
#pragma unroll
            for (int d = 0; d < 4; ++d) sP[tid][jj][d] = p3[jj][d];
    }
    __syncthreads();

    // A2: thread j combines pieces -> monomial Q_j
    if (tid < NJ) {
        int j = tid;
        double bb[4] = {0.0, 0.0, 0.0, 0.0};
        int ilo = (j - 3 < 0) ? 0 : j - 3;
        int ihi = (j < C_DIM - 1) ? j : C_DIM - 1;
        for (int i = ilo; i <= ihi; ++i) {
            int jj = j - i;
            double ci = sc[i];
#pragma unroll
            for (int d = 0; d < 4; ++d) bb[d] += ci * sP[i][jj][d];
        }
#pragma unroll
        for (int d = 0; d < 4; ++d) qm[j][d] = bb[d];
    }

    // B: thresholds
    if (tid < NTH) {
        if (tid < NJ) thr[tid] = t[s * T_DIM + tid];
        else {
            int j = tid - NJ;
            thr[tid] = fmaxf(t[s * T_DIM + j], t[s * T_DIM + j + 1]);
        }
    }
    __syncthreads();

    // C: rank sort (stable)
    if (tid < NTH) {
        float v = thr[tid];
        int r = 0;
        for (int i = 0; i < NTH; ++i) {
            float w = thr[i];
            r += (w < v) || (w == v && i < tid);
        }
        sth[r] = v;
        sidx[r] = tid;
    }
    __syncthreads();

    // D: signed pieces, inclusive scan
    if (tid < NTH) {
        int k = sidx[tid];
        int p = (k < NJ) ? k : k - NJ;
        double sgn = (k < NJ) ? 1.0 : -1.0;
#pragma unroll
        for (int d = 0; d < 4; ++d) sv[tid][d] = sgn * qm[p][d];
    }
    __syncthreads();
    for (int stp = 1; stp < NTH; stp <<= 1) {
        double tmp[4] = {0.0, 0.0, 0.0, 0.0};
        bool act = (tid < NTH) && (tid >= stp);
        if (act) {
#pragma unroll
            for (int d = 0; d < 4; ++d) tmp[d] = sv[tid - stp][d];
        }
        __syncthreads();
        if (act) {
#pragma unroll
            for (int d = 0; d < 4; ++d) sv[tid][d] += tmp[d];
        }
        __syncthreads();
    }

    // E: Taylor-center prefix poly m at sth[m-1]
    if (tid <= NTH) {
        int m = tid;
        float4 oc = make_float4(0.f, 0.f, 0.f, 0.f);
        if (m > 0) {
            double bb[4];
#pragma unroll
            for (int d = 0; d < 4; ++d) bb[d] = sv[m - 1][d];
            double tc = (double)sth[m - 1];
#pragma unroll
            for (int pass = 0; pass < 3; ++pass)
#pragma unroll
                for (int d = 2; d >= 0; --d)
                    if (d >= pass) bb[d] += tc * bb[d + 1];
            oc = make_float4((float)bb[0], (float)bb[1], (float)bb[2], (float)bb[3]);
        }
        g_C[s][m] = oc;
    }
    // F: padded sorted thresholds
    if (tid < NTH) g_th[s][tid + 1] = sth[tid];
    if (tid == 0)  g_th[s][0] = -CUDART_INF_F;
    if (tid < NTHP - NTH - 1) g_th[s][NTH + 1 + tid] = CUDART_INF_F;  // [135..139]

    // G: bucket table  bt[b] = #{th < edge_b}; edge_0 = -INF (bt[0] = 0)
    for (int b = tid; b < NB; b += blockDim.x) {
        int cnt = 0;
        if (b > 0) {
            float edge = -4.0f + (float)b * (1.0f / 64.0f);   // exact in fp32
            for (int i = 0; i < NTH; ++i) cnt += (sth[i] < edge);
        }
        g_bt[s][b] = (uint8_t)cnt;
    }
}

// ---------------------------------------------------------------------------
// Main kernel: bucket -> 5 parallel probes -> branchless count; cold
// warp-voted fallback loop guarantees exactness.
// ---------------------------------------------------------------------------
#define TH_STRIDE 141   // floats per spline (140 used), 141%32=13 coprime
#define C_STRIDE  137   // float4 per spline (135 used), odd
#define BT_WORDS  129   // words per spline bucket row (128 used), odd

extern __shared__ float dynsmem[];

__global__ __launch_bounds__(1024, 2)
void bspline_main_kernel(const float* __restrict__ x,
                         float* __restrict__ out, int B) {
    float*    sTh = dynsmem;                                  // 32*141 floats
    float4*   sC  = (float4*)(dynsmem + 32 * TH_STRIDE + 12); // pad to 16B align
    uint32_t* sBt = (uint32_t*)(sC + 32 * C_STRIDE);          // 32*129 words

    const int tid   = threadIdx.x;
    const int sBase = blockIdx.y * 32;

    for (int i = tid; i < 32 * NTHP; i += 1024) {
        int sp = i / NTHP, k = i - sp * NTHP;
        sTh[sp * TH_STRIDE + k] = g_th[sBase + sp][k];
    }
    for (int i = tid; i < 32 * NPF; i += 1024) {
        int sp = i / NPF, k = i - sp * NPF;
        sC[sp * C_STRIDE + k] = g_C[sBase + sp][k];
    }
    for (int i = tid; i < 32 * (NB / 4); i += 1024) {
        int sp = i >> 7, k = i & 127;
        sBt[sp * BT_WORDS + k] = ((const uint32_t*)g_bt[sBase + sp])[k];
    }
    __syncthreads();

    const int lane = tid & 31;
    const int warp = tid >> 5;
    const float*   tbv = &sTh[lane * TH_STRIDE];   // tbv[m] = th[m-1]; sentinels at both ends
    const float4*  cb  = &sC[lane * C_STRIDE];
    const uint8_t* btb = (const uint8_t*)&sBt[lane * BT_WORDS];
    const int col = sBase + lane;
    const int wstride = gridDim.x * 32;

    for (int row = blockIdx.x * 32 + warp; row < B; row += wstride) {
        float xv = x[row * N_SPLINES + col];

        int b = __float2int_rz((xv + 4.0f) * 64.0f);
        b = min(max(b, 0), NB - 1);
        int m0 = (int)btb[b];

        // 5 independent probes around the estimate
        float p0 = tbv[m0];
        float p1 = tbv[m0 + 1];
        float p2 = tbv[m0 + 2];
        float p3 = tbv[m0 + 3];
        float p4 = tbv[m0 + 4];

        int c1 = (p1 <= xv), c2 = (p2 <= xv), c3 = (p3 <= xv);
        int cnt = c1 + c2 + c3;
        bool bad = (p0 > xv) | (p4 <= xv);

        int   m;
        float v;
        if (__any_sync(0xFFFFFFFFu, bad)) {
            // exact fallback (cold): sentinel-terminated scans
            m = m0;
            while (tbv[m] > xv) --m;
            while (tbv[m + 1] <= xv) ++m;
            v = tbv[m];
        } else {
            m = m0 + cnt;
            v = (cnt == 0) ? p0 : ((cnt == 1) ? p1 : ((cnt == 2) ? p2 : p3));
        }

        float  ctr = (m > 0) ? v : 0.0f;       // m=0 poly is zero; avoid INF*0
        float4 cf  = cb[m];
        float  u   = xv - ctr;
        out[row * N_SPLINES + col] =
            fmaf(fmaf(fmaf(cf.w, u, cf.z), u, cf.y), u, cf.x);
    }
}

// ---------------------------------------------------------------------------
extern "C" void kernel_launch(void* const* d_in, const int* in_sizes, int n_in,
                              void* d_out, int out_size) {
    const float* x = (const float*)d_in[0];   // [B, 64]
    const float* t = (const float*)d_in[1];   // [64, 68]
    const float* c = (const float*)d_in[2];   // [64, 64]
    float* out = (float*)d_out;               // [B, 64]

    const int B = in_sizes[0] / N_SPLINES;    // 65536

    precompute_kernel<<<N_SPLINES, 256>>>(t, c);

    const size_t smemSz = (size_t)(32 * TH_STRIDE) * 4 + 48      // sTh + align pad
                        + (size_t)(32 * C_STRIDE) * 16           // sC
                        + (size_t)(32 * BT_WORDS) * 4;           // sBt  => ~105 KB
    cudaFuncSetAttribute(bspline_main_kernel,
                         cudaFuncAttributeMaxDynamicSharedMemorySize, (int)smemSz);

    dim3 grid(148, 2);
    bspline_main_kernel<<<grid, 1024, smemSz>>>(x, out, B);
}